// round 4
// baseline (speedup 1.0000x reference)
#include <cuda_runtime.h>

#define Bq 256
#define Pq 128
#define Kq 16
#define Hq 128
#define Oq 256
// E = 18, input row = 10 floats: [c0,c1,f0..f6,mask]

__device__ int   g_idx [Bq*Pq*Kq];
__device__ float g_base[Bq*Pq*Hq];
__device__ float g_y   [Bq*Pq*Hq];

// ---------------------------------------------------------------------------
// K1: exact KNN (top-17 by dist2, ties -> lower index, drop self)
// grid (B, 2), block 64: each block handles 64 points of one batch.
// ---------------------------------------------------------------------------
__global__ __launch_bounds__(64) void knn_kernel(const float* __restrict__ x) {
    const int b    = blockIdx.x;
    const int half = blockIdx.y;
    const int t    = threadIdx.x;            // 0..63

    __shared__ float scx[Pq], scy[Pq], sval[Pq];
    __shared__ float sdist[Pq * 64];         // [j][local p] column-per-thread

    for (int j = t; j < Pq; j += 64) {
        const float* row = x + ((size_t)b * Pq + j) * 10;
        scx[j]  = row[0];
        scy[j]  = row[1];
        sval[j] = row[9];
    }
    __syncthreads();

    const int p = half * 64 + t;
    if (sval[p] <= 0.f) return;              // masked row: neighbors unused

    const float cx = scx[p], cy = scy[p];
    for (int j = 0; j < Pq; j++) {
        float dx = scx[j] - cx;
        float dy = scy[j] - cy;
        float d  = dx * dx + dy * dy;
        if (sval[j] <= 0.f) d = 1e9f;        // BIG, matches reference mask
        sdist[j * 64 + t] = d;
    }

    const int out_off = (b * Pq + p) * Kq;
    #pragma unroll 1
    for (int pass = 0; pass < Kq + 1; pass++) {
        float best = 3.0e38f;
        int   bj   = 0;
        for (int j = 0; j < Pq; j++) {
            float d = sdist[j * 64 + t];
            if (d < best) { best = d; bj = j; }   // strict < : lowest idx wins ties
        }
        sdist[bj * 64 + t] = 3.4e38f;
        if (pass >= 1) g_idx[out_off + pass - 1] = bj;   // pass 0 = self
    }
}

// ---------------------------------------------------------------------------
// K2: base[p] = pt * (W1[0:9] - W1[9:18]) + b1 ;  y[p] = pt * W1[9:18]
// grid B*P, block 128 (one thread per hidden unit).
// ---------------------------------------------------------------------------
__global__ __launch_bounds__(128) void embed_kernel(const float* __restrict__ x,
                                                    const float* __restrict__ W1,
                                                    const float* __restrict__ b1) {
    const int bp = blockIdx.x;
    const int h  = threadIdx.x;
    const float* row = x + (size_t)bp * 10;

    float base = b1[h];
    float y    = 0.f;
    #pragma unroll
    for (int e = 0; e < 9; e++) {
        float v  = row[e];                       // warp-uniform broadcast load
        float wa = W1[e * Hq + h];
        float wb = W1[(e + 9) * Hq + h];
        base = fmaf(v, wa - wb, base);
        y    = fmaf(v, wb, y);
    }
    g_base[(size_t)bp * Hq + h] = base;
    g_y   [(size_t)bp * Hq + h] = y;
}

// ---------------------------------------------------------------------------
// K3: per point: h1 = relu(base + y[nbr]) (16x128, smem) ; h2 = relu(h1@W2+b2);
//     out = mean_k(h2) ++ [1.0]. grid B*P, block 128, 2 output cols/thread.
// ---------------------------------------------------------------------------
__global__ __launch_bounds__(128) void mlp_kernel(const float* __restrict__ x,
                                                  const float* __restrict__ W2,
                                                  const float* __restrict__ b2,
                                                  float* __restrict__ out) {
    const int bp = blockIdx.x;
    const int t  = threadIdx.x;
    float* orow = out + (size_t)bp * (Oq + 1);

    const float mask = x[(size_t)bp * 10 + 9];
    if (mask <= 0.f) {                            // masked row -> zeros
        for (int i = t; i < Oq + 1; i += 128) orow[i] = 0.f;
        return;
    }

    __shared__ __align__(16) float h1s[Kq][Hq];   // 8 KB
    __shared__ int sidx[Kq];

    const int b = bp >> 7;                        // bp / P
    if (t < Kq) sidx[t] = g_idx[(size_t)bp * Kq + t];
    __syncthreads();

    const float basev = g_base[(size_t)bp * Hq + t];
    #pragma unroll
    for (int m = 0; m < Kq; m++) {
        int nb  = sidx[m];
        float v = basev + g_y[((size_t)b * Pq + nb) * Hq + t];
        h1s[m][t] = fmaxf(v, 0.f);
    }
    __syncthreads();

    float acc0[Kq], acc1[Kq];
    #pragma unroll
    for (int m = 0; m < Kq; m++) { acc0[m] = 0.f; acc1[m] = 0.f; }

    const float* w2 = W2 + t;                     // cols t and t+128
    #pragma unroll 2
    for (int k = 0; k < Hq; k += 4) {
        float w00 = w2[(k + 0) * Oq], w01 = w2[(k + 0) * Oq + 128];
        float w10 = w2[(k + 1) * Oq], w11 = w2[(k + 1) * Oq + 128];
        float w20 = w2[(k + 2) * Oq], w21 = w2[(k + 2) * Oq + 128];
        float w30 = w2[(k + 3) * Oq], w31 = w2[(k + 3) * Oq + 128];
        #pragma unroll
        for (int m = 0; m < Kq; m++) {
            float4 hv = *reinterpret_cast<const float4*>(&h1s[m][k]);
            acc0[m] = fmaf(hv.x, w00, acc0[m]);  acc1[m] = fmaf(hv.x, w01, acc1[m]);
            acc0[m] = fmaf(hv.y, w10, acc0[m]);  acc1[m] = fmaf(hv.y, w11, acc1[m]);
            acc0[m] = fmaf(hv.z, w20, acc0[m]);  acc1[m] = fmaf(hv.z, w21, acc1[m]);
            acc0[m] = fmaf(hv.w, w30, acc0[m]);  acc1[m] = fmaf(hv.w, w31, acc1[m]);
        }
    }

    const float bb0 = b2[t], bb1 = b2[t + 128];
    float s0 = 0.f, s1 = 0.f;
    #pragma unroll
    for (int m = 0; m < Kq; m++) {
        s0 += fmaxf(acc0[m] + bb0, 0.f);
        s1 += fmaxf(acc1[m] + bb1, 0.f);
    }
    orow[t]       = s0 * (1.f / 16.f);
    orow[t + 128] = s1 * (1.f / 16.f);
    if (t == 0) orow[Oq] = 1.f;
}

// ---------------------------------------------------------------------------
extern "C" void kernel_launch(void* const* d_in, const int* in_sizes, int n_in,
                              void* d_out, int out_size) {
    (void)in_sizes; (void)n_in; (void)out_size;
    const float* x  = (const float*)d_in[0];   // (256,128,10)
    const float* W1 = (const float*)d_in[1];   // (18,128)
    const float* b1 = (const float*)d_in[2];   // (128,)
    const float* W2 = (const float*)d_in[3];   // (128,256)
    const float* b2 = (const float*)d_in[4];   // (256,)
    float* out = (float*)d_out;                // (256,128,257)

    knn_kernel<<<dim3(Bq, 2), 64>>>(x);
    embed_kernel<<<Bq * Pq, Hq>>>(x, W1, b1);
    mlp_kernel<<<Bq * Pq, Hq>>>(x, W2, b2, out);
}

// round 5
// speedup vs baseline: 1.0012x; 1.0012x over previous
#include <cuda_runtime.h>

#define Bq 256
#define Pq 128
#define Kq 16
#define Hq 128
#define Oq 256
// E = 18, input row = 10 floats: [c0,c1,f0..f6,mask]

__device__ int   g_idx [Bq*Pq*Kq];
__device__ float g_base[Bq*Pq*Hq];
__device__ float g_y   [Bq*Pq*Hq];

// ---------------------------------------------------------------------------
// K1: exact KNN (top-17 by dist2, ties -> lower index, drop self)
// grid (B, 2), block 64: each block handles 64 points of one batch.
// ---------------------------------------------------------------------------
__global__ __launch_bounds__(64) void knn_kernel(const float* __restrict__ x) {
    const int b    = blockIdx.x;
    const int half = blockIdx.y;
    const int t    = threadIdx.x;            // 0..63

    __shared__ float scx[Pq], scy[Pq], sval[Pq];
    __shared__ float sdist[Pq * 64];         // [j][local p] column-per-thread

    for (int j = t; j < Pq; j += 64) {
        const float* row = x + ((size_t)b * Pq + j) * 10;
        scx[j]  = row[0];
        scy[j]  = row[1];
        sval[j] = row[9];
    }
    __syncthreads();

    const int p = half * 64 + t;
    if (sval[p] <= 0.f) return;              // masked row: neighbors unused

    const float cx = scx[p], cy = scy[p];
    for (int j = 0; j < Pq; j++) {
        float dx = scx[j] - cx;
        float dy = scy[j] - cy;
        float d  = dx * dx + dy * dy;
        if (sval[j] <= 0.f) d = 1e9f;        // BIG, matches reference mask
        sdist[j * 64 + t] = d;
    }

    const int out_off = (b * Pq + p) * Kq;
    #pragma unroll 1
    for (int pass = 0; pass < Kq + 1; pass++) {
        float best = 3.0e38f;
        int   bj   = 0;
        for (int j = 0; j < Pq; j++) {
            float d = sdist[j * 64 + t];
            if (d < best) { best = d; bj = j; }   // strict < : lowest idx wins ties
        }
        sdist[bj * 64 + t] = 3.4e38f;
        if (pass >= 1) g_idx[out_off + pass - 1] = bj;   // pass 0 = self
    }
}

// ---------------------------------------------------------------------------
// K2: base[p] = pt * (W1[0:9] - W1[9:18]) + b1 ;  y[p] = pt * W1[9:18]
// grid B*P, block 128 (one thread per hidden unit).
// ---------------------------------------------------------------------------
__global__ __launch_bounds__(128) void embed_kernel(const float* __restrict__ x,
                                                    const float* __restrict__ W1,
                                                    const float* __restrict__ b1) {
    const int bp = blockIdx.x;
    const int h  = threadIdx.x;
    const float* row = x + (size_t)bp * 10;

    float base = b1[h];
    float y    = 0.f;
    #pragma unroll
    for (int e = 0; e < 9; e++) {
        float v  = row[e];                       // warp-uniform broadcast load
        float wa = W1[e * Hq + h];
        float wb = W1[(e + 9) * Hq + h];
        base = fmaf(v, wa - wb, base);
        y    = fmaf(v, wb, y);
    }
    g_base[(size_t)bp * Hq + h] = base;
    g_y   [(size_t)bp * Hq + h] = y;
}

// ---------------------------------------------------------------------------
// K3: per point: h1 = relu(base + y[nbr]) (16x128, smem) ; h2 = relu(h1@W2+b2);
//     out = mean_k(h2) ++ [1.0]. grid B*P, block 128, 2 output cols/thread.
// ---------------------------------------------------------------------------
__global__ __launch_bounds__(128) void mlp_kernel(const float* __restrict__ x,
                                                  const float* __restrict__ W2,
                                                  const float* __restrict__ b2,
                                                  float* __restrict__ out) {
    const int bp = blockIdx.x;
    const int t  = threadIdx.x;
    float* orow = out + (size_t)bp * (Oq + 1);

    const float mask = x[(size_t)bp * 10 + 9];
    if (mask <= 0.f) {                            // masked row -> zeros
        for (int i = t; i < Oq + 1; i += 128) orow[i] = 0.f;
        return;
    }

    __shared__ __align__(16) float h1s[Kq][Hq];   // 8 KB
    __shared__ int sidx[Kq];

    const int b = bp >> 7;                        // bp / P
    if (t < Kq) sidx[t] = g_idx[(size_t)bp * Kq + t];
    __syncthreads();

    const float basev = g_base[(size_t)bp * Hq + t];
    #pragma unroll
    for (int m = 0; m < Kq; m++) {
        int nb  = sidx[m];
        float v = basev + g_y[((size_t)b * Pq + nb) * Hq + t];
        h1s[m][t] = fmaxf(v, 0.f);
    }
    __syncthreads();

    float acc0[Kq], acc1[Kq];
    #pragma unroll
    for (int m = 0; m < Kq; m++) { acc0[m] = 0.f; acc1[m] = 0.f; }

    const float* w2 = W2 + t;                     // cols t and t+128
    #pragma unroll 2
    for (int k = 0; k < Hq; k += 4) {
        float w00 = w2[(k + 0) * Oq], w01 = w2[(k + 0) * Oq + 128];
        float w10 = w2[(k + 1) * Oq], w11 = w2[(k + 1) * Oq + 128];
        float w20 = w2[(k + 2) * Oq], w21 = w2[(k + 2) * Oq + 128];
        float w30 = w2[(k + 3) * Oq], w31 = w2[(k + 3) * Oq + 128];
        #pragma unroll
        for (int m = 0; m < Kq; m++) {
            float4 hv = *reinterpret_cast<const float4*>(&h1s[m][k]);
            acc0[m] = fmaf(hv.x, w00, acc0[m]);  acc1[m] = fmaf(hv.x, w01, acc1[m]);
            acc0[m] = fmaf(hv.y, w10, acc0[m]);  acc1[m] = fmaf(hv.y, w11, acc1[m]);
            acc0[m] = fmaf(hv.z, w20, acc0[m]);  acc1[m] = fmaf(hv.z, w21, acc1[m]);
            acc0[m] = fmaf(hv.w, w30, acc0[m]);  acc1[m] = fmaf(hv.w, w31, acc1[m]);
        }
    }

    const float bb0 = b2[t], bb1 = b2[t + 128];
    float s0 = 0.f, s1 = 0.f;
    #pragma unroll
    for (int m = 0; m < Kq; m++) {
        s0 += fmaxf(acc0[m] + bb0, 0.f);
        s1 += fmaxf(acc1[m] + bb1, 0.f);
    }
    orow[t]       = s0 * (1.f / 16.f);
    orow[t + 128] = s1 * (1.f / 16.f);
    if (t == 0) orow[Oq] = 1.f;
}

// ---------------------------------------------------------------------------
extern "C" void kernel_launch(void* const* d_in, const int* in_sizes, int n_in,
                              void* d_out, int out_size) {
    (void)in_sizes; (void)n_in; (void)out_size;
    const float* x  = (const float*)d_in[0];   // (256,128,10)
    const float* W1 = (const float*)d_in[1];   // (18,128)
    const float* b1 = (const float*)d_in[2];   // (128,)
    const float* W2 = (const float*)d_in[3];   // (128,256)
    const float* b2 = (const float*)d_in[4];   // (256,)
    float* out = (float*)d_out;                // (256,128,257)

    knn_kernel<<<dim3(Bq, 2), 64>>>(x);
    embed_kernel<<<Bq * Pq, Hq>>>(x, W1, b1);
    mlp_kernel<<<Bq * Pq, Hq>>>(x, W2, b2, out);
}

// round 7
// speedup vs baseline: 1.7172x; 1.7151x over previous
#include <cuda_runtime.h>
#include <cuda_bf16.h>

#define Bq 256
#define Pq 128
#define Kq 16
#define Hq 128
#define Oq 256
#define LDH 136   // padded bf16 row stride

__device__ int   g_idx [Bq*Pq*Kq];
__device__ float g_base[Bq*Pq*Hq];
__device__ float g_y   [Bq*Pq*Hq];
__device__ __align__(16) __nv_bfloat16 g_wB[Oq*LDH];
__device__ __align__(16) __nv_bfloat16 g_wS[Oq*LDH];
__device__ int g_cnt;
__device__ int g_list[Bq*Pq];

// ---------------- K1: exact KNN (top-17, ties->lower idx, drop self) -------
__global__ __launch_bounds__(64) void knn_kernel(const float* __restrict__ x) {
    const int b = blockIdx.x, half = blockIdx.y, t = threadIdx.x;
    __shared__ float scx[Pq], scy[Pq], sval[Pq];
    __shared__ float sdist[Pq * 64];
    for (int j = t; j < Pq; j += 64) {
        const float* row = x + ((size_t)b * Pq + j) * 10;
        scx[j] = row[0]; scy[j] = row[1]; sval[j] = row[9];
    }
    __syncthreads();
    const int p = half * 64 + t;
    if (sval[p] <= 0.f) return;
    const float cx = scx[p], cy = scy[p];
    for (int j = 0; j < Pq; j++) {
        float dx = scx[j] - cx, dy = scy[j] - cy;
        float d = dx * dx + dy * dy;
        if (sval[j] <= 0.f) d = 1e9f;
        sdist[j * 64 + t] = d;
    }
    const int off = (b * Pq + p) * Kq;
    #pragma unroll 1
    for (int pass = 0; pass < Kq + 1; pass++) {
        float best = 3.0e38f; int bj = 0;
        for (int j = 0; j < Pq; j++) {
            float d = sdist[j * 64 + t];
            if (d < best) { best = d; bj = j; }
        }
        sdist[bj * 64 + t] = 3.4e38f;
        if (pass >= 1) g_idx[off + pass - 1] = bj;
    }
}

// ---------------- K2: layer-1 factorization --------------------------------
__global__ __launch_bounds__(128) void embed_kernel(const float* __restrict__ x,
                                                    const float* __restrict__ W1,
                                                    const float* __restrict__ b1) {
    const int bp = blockIdx.x, h = threadIdx.x;
    const float* row = x + (size_t)bp * 10;
    float base = b1[h], y = 0.f;
    #pragma unroll
    for (int e = 0; e < 9; e++) {
        float v = row[e];
        float wa = W1[e * Hq + h], wb = W1[(e + 9) * Hq + h];
        base = fmaf(v, wa - wb, base);
        y    = fmaf(v, wb, y);
    }
    g_base[(size_t)bp * Hq + h] = base;
    g_y   [(size_t)bp * Hq + h] = y;
}

// ---------------- prep: split W2 -> bf16 big/small, transposed+padded ------
__global__ __launch_bounds__(128) void prep_kernel(const float* __restrict__ W2) {
    const int i = blockIdx.x * 128 + threadIdx.x;     // i = k*256 + n
    if (i == 0) g_cnt = 0;
    g_list[i] = 0;                                    // padding -> point 0 (always live)
    const int k = i >> 8, n = i & 255;
    float w = W2[i];
    __nv_bfloat16 big = __float2bfloat16(w);
    g_wB[n * LDH + k] = big;
    g_wS[n * LDH + k] = __float2bfloat16(w - __bfloat162float(big));
}

// ---------------- compact: live list + dead-row zero + trailing 1 ----------
__global__ __launch_bounds__(256) void compact_kernel(const float* __restrict__ x,
                                                      float* __restrict__ out) {
    const int w = (blockIdx.x * blockDim.x + threadIdx.x) >> 5;
    const int l = threadIdx.x & 31;
    if (w >= Bq * Pq) return;
    float* orow = out + (size_t)w * (Oq + 1);
    if (x[(size_t)w * 10 + 9] > 0.f) {
        if (l == 0) { int s = atomicAdd(&g_cnt, 1); g_list[s] = w; orow[Oq] = 1.f; }
    } else {
        for (int j = l; j < Oq + 1; j += 32) orow[j] = 0.f;
    }
}

// ---------------- K3: persistent tensor-core MLP ---------------------------
__device__ __forceinline__ void mma_bf16(float* d, const unsigned* a,
                                         unsigned b0, unsigned b1) {
    asm volatile(
        "mma.sync.aligned.m16n8k16.row.col.f32.bf16.bf16.f32 "
        "{%0,%1,%2,%3},{%4,%5,%6,%7},{%8,%9},{%0,%1,%2,%3};"
        : "+f"(d[0]), "+f"(d[1]), "+f"(d[2]), "+f"(d[3])
        : "r"(a[0]), "r"(a[1]), "r"(a[2]), "r"(a[3]), "r"(b0), "r"(b1));
}

__global__ __launch_bounds__(256, 1) void mlp_kernel(const float* __restrict__ b2,
                                                     float* __restrict__ out) {
    extern __shared__ __nv_bfloat16 sm[];
    __nv_bfloat16* hB = sm;                 // [128][136]
    __nv_bfloat16* hS = hB + 128 * LDH;
    __nv_bfloat16* wB = hS + 128 * LDH;     // [256][136]
    __nv_bfloat16* wS = wB + Oq * LDH;
    __shared__ int s_pts[8];

    const int tid = threadIdx.x;
    {   // stage pre-split W2^T once per block
        const float4* sB = (const float4*)g_wB; const float4* sS = (const float4*)g_wS;
        float4* dB = (float4*)wB; float4* dS = (float4*)wS;
        for (int j = tid; j < Oq * LDH / 8; j += 256) { dB[j] = sB[j]; dS[j] = sS[j]; }
    }
    const int warp = tid >> 5, lane = tid & 31, g = lane >> 2, t4 = lane & 3;
    const int pg = warp >> 2, nch = warp & 3, n0 = nch * 64;

    float bias[8][2];
    #pragma unroll
    for (int nt = 0; nt < 8; nt++) {
        bias[nt][0] = b2[n0 + nt * 8 + 2 * t4];
        bias[nt][1] = b2[n0 + nt * 8 + 2 * t4 + 1];
    }

    const int cnt = g_cnt;
    const int ngrp = (cnt + 7) >> 3;
    for (int grp = blockIdx.x; grp < ngrp; grp += gridDim.x) {
        __syncthreads();                      // staging / prev-iter reads done
        if (tid < 8) s_pts[tid] = g_list[grp * 8 + tid];
        __syncthreads();

        {   // h1 = relu(base + y[nbr]) -> bf16 big/small (thread = row,half)
            const int row = tid >> 1, half = tid & 1;
            const int point = s_pts[row >> 4], m = row & 15;
            const int nb = g_idx[point * Kq + m];
            const int bb_ = point >> 7;
            const float4* yv = (const float4*)(g_y + (size_t)(bb_ * Pq + nb) * Hq) + half * 16;
            const float4* bv = (const float4*)(g_base + (size_t)point * Hq) + half * 16;
            __nv_bfloat16* pB = hB + row * LDH + half * 64;
            __nv_bfloat16* pS = hS + row * LDH + half * 64;
            #pragma unroll
            for (int j = 0; j < 16; j++) {
                float4 yy = yv[j], bv4 = bv[j];
                float v0 = fmaxf(bv4.x + yy.x, 0.f), v1 = fmaxf(bv4.y + yy.y, 0.f);
                float v2 = fmaxf(bv4.z + yy.z, 0.f), v3 = fmaxf(bv4.w + yy.w, 0.f);
                __nv_bfloat162 g0; g0.x = __float2bfloat16(v0); g0.y = __float2bfloat16(v1);
                __nv_bfloat162 g1; g1.x = __float2bfloat16(v2); g1.y = __float2bfloat16(v3);
                *(__nv_bfloat162*)(pB + 4 * j)     = g0;
                *(__nv_bfloat162*)(pB + 4 * j + 2) = g1;
                __nv_bfloat162 s0, s1;
                s0.x = __float2bfloat16(v0 - __bfloat162float(g0.x));
                s0.y = __float2bfloat16(v1 - __bfloat162float(g0.y));
                s1.x = __float2bfloat16(v2 - __bfloat162float(g1.x));
                s1.y = __float2bfloat16(v3 - __bfloat162float(g1.y));
                *(__nv_bfloat162*)(pS + 4 * j)     = s0;
                *(__nv_bfloat162*)(pS + 4 * j + 2) = s1;
            }
        }
        __syncthreads();

        float acc[4][8][4];
        #pragma unroll
        for (int i = 0; i < 4; i++)
            #pragma unroll
            for (int nt = 0; nt < 8; nt++)
                #pragma unroll
                for (int c = 0; c < 4; c++) acc[i][nt][c] = 0.f;

        #pragma unroll 1
        for (int s = 0; s < 8; s++) {
            unsigned aB[4][4], aS[4][4];
            #pragma unroll
            for (int i = 0; i < 4; i++) {
                const int r = (pg * 4 + i) * 16 + g;
                const unsigned* p = (const unsigned*)(hB + r * LDH + s * 16) + t4;
                const unsigned* q = (const unsigned*)(hS + r * LDH + s * 16) + t4;
                aB[i][0] = p[0]; aB[i][1] = p[544]; aB[i][2] = p[4]; aB[i][3] = p[548];
                aS[i][0] = q[0]; aS[i][1] = q[544]; aS[i][2] = q[4]; aS[i][3] = q[548];
            }
            #pragma unroll
            for (int nt = 0; nt < 8; nt++) {
                const int n = n0 + nt * 8 + g;
                const unsigned* p = (const unsigned*)(wB + n * LDH + s * 16) + t4;
                const unsigned* q = (const unsigned*)(wS + n * LDH + s * 16) + t4;
                unsigned bB0 = p[0], bB1 = p[4], bS0 = q[0], bS1 = q[4];
                #pragma unroll
                for (int i = 0; i < 4; i++) {
                    mma_bf16(acc[i][nt], aB[i], bB0, bB1);
                    mma_bf16(acc[i][nt], aB[i], bS0, bS1);
                    mma_bf16(acc[i][nt], aS[i], bB0, bB1);
                }
            }
        }

        // epilogue: relu(+bias), mean over 16 rows (lanes g, g+8 -> shfl over g)
        #pragma unroll
        for (int i = 0; i < 4; i++) {
            const int point = s_pts[pg * 4 + i];
            float* orow = out + (size_t)point * (Oq + 1);
            #pragma unroll
            for (int nt = 0; nt < 8; nt++) {
                float s0 = fmaxf(acc[i][nt][0] + bias[nt][0], 0.f)
                         + fmaxf(acc[i][nt][2] + bias[nt][0], 0.f);
                float s1 = fmaxf(acc[i][nt][1] + bias[nt][1], 0.f)
                         + fmaxf(acc[i][nt][3] + bias[nt][1], 0.f);
                #pragma unroll
                for (int o = 4; o < 32; o <<= 1) {
                    s0 += __shfl_xor_sync(0xffffffffu, s0, o);
                    s1 += __shfl_xor_sync(0xffffffffu, s1, o);
                }
                if (g == 0) {
                    orow[n0 + nt * 8 + 2 * t4]     = s0 * (1.f / 16.f);
                    orow[n0 + nt * 8 + 2 * t4 + 1] = s1 * (1.f / 16.f);
                }
            }
        }
    }
}

// ---------------------------------------------------------------------------
extern "C" void kernel_launch(void* const* d_in, const int* in_sizes, int n_in,
                              void* d_out, int out_size) {
    (void)in_sizes; (void)n_in; (void)out_size;
    const float* x  = (const float*)d_in[0];
    const float* W1 = (const float*)d_in[1];
    const float* b1 = (const float*)d_in[2];
    const float* W2 = (const float*)d_in[3];
    const float* b2 = (const float*)d_in[4];
    float* out = (float*)d_out;

    const int smem = (128 * LDH + 128 * LDH + Oq * LDH + Oq * LDH) * 2;  // 208896 B
    cudaFuncSetAttribute(mlp_kernel, cudaFuncAttributeMaxDynamicSharedMemorySize, smem);

    prep_kernel<<<256, 128>>>(W2);
    knn_kernel<<<dim3(Bq, 2), 64>>>(x);
    embed_kernel<<<Bq * Pq, Hq>>>(x, W1, b1);
    compact_kernel<<<(Bq * Pq * 32) / 256, 256>>>(x, out);
    mlp_kernel<<<148, 256, smem>>>(b2, out);
}

// round 10
// speedup vs baseline: 1.8488x; 1.0766x over previous
#include <cuda_runtime.h>
#include <cuda_bf16.h>
#include <cstdint>

#define Bq 256
#define Pq 128
#define Kq 16
#define Hq 128
#define Oq 256
#define LDH 136            // padded row stride (elements); 272 bytes

__device__ int   g_idx [Bq*Pq*Kq];
__device__ float g_base[Bq*Pq*Hq];
__device__ float g_y   [Bq*Pq*Hq];
__device__ __align__(16) __nv_bfloat16 g_wB[Oq*LDH];   // W2^T big  [n][k]
__device__ __align__(16) __nv_bfloat16 g_wS[Oq*LDH];   // W2^T small[n][k]
__device__ int g_cnt;
__device__ int g_list[Bq*Pq];

// ---------------- K1: exact KNN (top-17, ties->lower idx, drop self) -------
__global__ __launch_bounds__(64) void knn_kernel(const float* __restrict__ x) {
    const int b = blockIdx.x, half = blockIdx.y, t = threadIdx.x;
    __shared__ float scx[Pq], scy[Pq], sval[Pq];
    __shared__ float sdist[Pq * 64];
    for (int j = t; j < Pq; j += 64) {
        const float* row = x + ((size_t)b * Pq + j) * 10;
        scx[j] = row[0]; scy[j] = row[1]; sval[j] = row[9];
    }
    __syncthreads();
    const int p = half * 64 + t;
    if (sval[p] <= 0.f) return;
    const float cx = scx[p], cy = scy[p];
    for (int j = 0; j < Pq; j++) {
        float dx = scx[j] - cx, dy = scy[j] - cy;
        float d = dx * dx + dy * dy;
        if (sval[j] <= 0.f) d = 1e9f;
        sdist[j * 64 + t] = d;
    }
    const int off = (b * Pq + p) * Kq;
    #pragma unroll 1
    for (int pass = 0; pass < Kq + 1; pass++) {
        float best = 3.0e38f; int bj = 0;
        for (int j = 0; j < Pq; j++) {
            float d = sdist[j * 64 + t];
            if (d < best) { best = d; bj = j; }
        }
        sdist[bj * 64 + t] = 3.4e38f;
        if (pass >= 1) g_idx[off + pass - 1] = bj;
    }
}

// ---------------- K2: layer-1 factorization --------------------------------
__global__ __launch_bounds__(128) void embed_kernel(const float* __restrict__ x,
                                                    const float* __restrict__ W1,
                                                    const float* __restrict__ b1) {
    const int bp = blockIdx.x, h = threadIdx.x;
    const float* row = x + (size_t)bp * 10;
    float base = b1[h], y = 0.f;
    #pragma unroll
    for (int e = 0; e < 9; e++) {
        float v = row[e];
        float wa = W1[e * Hq + h], wb = W1[(e + 9) * Hq + h];
        base = fmaf(v, wa - wb, base);
        y    = fmaf(v, wb, y);
    }
    g_base[(size_t)bp * Hq + h] = base;
    g_y   [(size_t)bp * Hq + h] = y;
}

// ---------------- prep: W2 -> big/small bf16, transposed [n][k]+pad --------
__global__ __launch_bounds__(128) void prep_kernel(const float* __restrict__ W2) {
    const int i = blockIdx.x * 128 + threadIdx.x;   // i = k*256 + n
    if (i == 0) g_cnt = 0;
    g_list[i] = 0;                                  // pad slots -> point 0 (always live)
    const int k = i >> 8, n = i & 255;
    float w = W2[i];
    __nv_bfloat16 big = __float2bfloat16(w);
    g_wB[n * LDH + k] = big;
    g_wS[n * LDH + k] = __float2bfloat16(w - __bfloat162float(big));
}

// ---------------- zero output + live list ----------------------------------
__global__ void zero_kernel(float4* __restrict__ o, int n4) {
    int i = blockIdx.x * blockDim.x + threadIdx.x;
    const int stride = gridDim.x * blockDim.x;
    const float4 z = make_float4(0.f, 0.f, 0.f, 0.f);
    for (; i < n4; i += stride) o[i] = z;
}
__global__ __launch_bounds__(256) void list_kernel(const float* __restrict__ x) {
    const int p = blockIdx.x * 256 + threadIdx.x;
    if (p >= Bq * Pq) return;
    if (x[(size_t)p * 10 + 9] > 0.f) { int s = atomicAdd(&g_cnt, 1); g_list[s] = p; }
}

// ---------------- helpers --------------------------------------------------
__device__ __forceinline__ uint32_t smem_u32(const void* p) {
    uint32_t a;
    asm("{ .reg .u64 t; cvta.to.shared.u64 t, %1; cvt.u32.u64 %0, t; }" : "=r"(a) : "l"(p));
    return a;
}
__device__ __forceinline__ void mma_bf16(float* d, const unsigned* a,
                                         unsigned b0, unsigned b1) {
    asm volatile(
        "mma.sync.aligned.m16n8k16.row.col.f32.bf16.bf16.f32 "
        "{%0,%1,%2,%3},{%4,%5,%6,%7},{%8,%9},{%0,%1,%2,%3};"
        : "+f"(d[0]), "+f"(d[1]), "+f"(d[2]), "+f"(d[3])
        : "r"(a[0]), "r"(a[1]), "r"(a[2]), "r"(a[3]), "r"(b0), "r"(b1));
}
#define LDSM_X4(r, addr) \
    asm volatile("ldmatrix.sync.aligned.m8n8.x4.shared.b16 {%0,%1,%2,%3}, [%4];" \
        : "=r"((r)[0]), "=r"((r)[1]), "=r"((r)[2]), "=r"((r)[3]) : "r"(addr))

#define A_SMALL_OFF 34816u   // 128*272
#define B_BASE_OFF  69632u   // after A big+small
#define B_SMALL_OFF 69632u   // wS = wB + 256*272

// ---------------- K3: persistent mma.sync MLP (ldmatrix fragments) ---------
__global__ __launch_bounds__(256, 1) void mlp_kernel(const float* __restrict__ b2,
                                                     float* __restrict__ out) {
    extern __shared__ __align__(16) char dyn[];
    __nv_bfloat16* hB = (__nv_bfloat16*)dyn;                 // [128][136]
    __nv_bfloat16* wB = (__nv_bfloat16*)(dyn + B_BASE_OFF);  // [256][136] big+small
    __shared__ int s_pts[8];

    const int tid = threadIdx.x, warp = tid >> 5, lane = tid & 31;
    const int t4 = lane & 3;
    const int pg = warp >> 2, nch = warp & 3, n0 = nch * 64;
    const uint32_t sbase = smem_u32(dyn);

    {   // stage pre-split W2^T once per block (linear copy, layout preserved)
        const float4* sB = (const float4*)g_wB; const float4* sS = (const float4*)g_wS;
        float4* dB = (float4*)(dyn + B_BASE_OFF);
        float4* dS = (float4*)(dyn + B_BASE_OFF + B_SMALL_OFF);
        for (int j = tid; j < Oq * LDH / 8; j += 256) { dB[j] = sB[j]; dS[j] = sS[j]; }
    }

    // per-lane ldmatrix base addresses
    uint32_t aAddr[4];
    #pragma unroll
    for (int i = 0; i < 4; i++)
        aAddr[i] = sbase + ((pg * 4 + i) * 16 + (lane & 15)) * 272 + (lane >> 4) * 16;
    uint32_t bAddr[4];
    #pragma unroll
    for (int j = 0; j < 4; j++)
        bAddr[j] = sbase + B_BASE_OFF +
                   (n0 + j * 16 + (lane & 7) + ((lane >> 4) << 3)) * 272 +
                   ((lane >> 3) & 1) * 16;

    float bias[8][2];
    #pragma unroll
    for (int nt = 0; nt < 8; nt++) {
        bias[nt][0] = b2[n0 + nt * 8 + 2 * t4];
        bias[nt][1] = b2[n0 + nt * 8 + 2 * t4 + 1];
    }
    __syncthreads();

    const int cnt = g_cnt, ngrp = (cnt + 7) >> 3;
    for (int grp = blockIdx.x; grp < ngrp; grp += gridDim.x) {
        if (tid < 8) s_pts[tid] = g_list[grp * 8 + tid];
        __syncthreads();

        {   // h1 = relu(base + y[nbr]) -> bf16 big/small rows (stride 272B)
            const int row = tid >> 1, half = tid & 1;
            const int point = s_pts[tid >> 5], m = row & 15;
            const int nb = g_idx[point * Kq + m];
            const int bat = point >> 7;
            const float4* yv = (const float4*)(g_y + (size_t)(bat * Pq + nb) * Hq) + half * 16;
            const float4* bv = (const float4*)(g_base + (size_t)point * Hq) + half * 16;
            char* pB = dyn + row * 272 + half * 128;
            char* pS = pB + A_SMALL_OFF;
            #pragma unroll
            for (int c = 0; c < 8; c++) {
                float4 ya = yv[2 * c],     ba  = bv[2 * c];
                float4 yb = yv[2 * c + 1], bbv = bv[2 * c + 1];
                float v0 = fmaxf(ba.x + ya.x, 0.f),  v1 = fmaxf(ba.y + ya.y, 0.f);
                float v2 = fmaxf(ba.z + ya.z, 0.f),  v3 = fmaxf(ba.w + ya.w, 0.f);
                float v4 = fmaxf(bbv.x + yb.x, 0.f), v5 = fmaxf(bbv.y + yb.y, 0.f);
                float v6 = fmaxf(bbv.z + yb.z, 0.f), v7 = fmaxf(bbv.w + yb.w, 0.f);
                __nv_bfloat162 h0, h1_, h2, h3;
                h0.x = __float2bfloat16(v0);  h0.y = __float2bfloat16(v1);
                h1_.x = __float2bfloat16(v2); h1_.y = __float2bfloat16(v3);
                h2.x = __float2bfloat16(v4);  h2.y = __float2bfloat16(v5);
                h3.x = __float2bfloat16(v6);  h3.y = __float2bfloat16(v7);
                uint4 bq;
                bq.x = *(uint32_t*)&h0; bq.y = *(uint32_t*)&h1_;
                bq.z = *(uint32_t*)&h2; bq.w = *(uint32_t*)&h3;
                __nv_bfloat162 t0, t1, t2, t3;
                t0.x = __float2bfloat16(v0 - __bfloat162float(h0.x));
                t0.y = __float2bfloat16(v1 - __bfloat162float(h0.y));
                t1.x = __float2bfloat16(v2 - __bfloat162float(h1_.x));
                t1.y = __float2bfloat16(v3 - __bfloat162float(h1_.y));
                t2.x = __float2bfloat16(v4 - __bfloat162float(h2.x));
                t2.y = __float2bfloat16(v5 - __bfloat162float(h2.y));
                t3.x = __float2bfloat16(v6 - __bfloat162float(h3.x));
                t3.y = __float2bfloat16(v7 - __bfloat162float(h3.y));
                uint4 sq;
                sq.x = *(uint32_t*)&t0; sq.y = *(uint32_t*)&t1;
                sq.z = *(uint32_t*)&t2; sq.w = *(uint32_t*)&t3;
                *(uint4*)(pB + 16 * c) = bq;
                *(uint4*)(pS + 16 * c) = sq;
            }
        }
        __syncthreads();

        float acc[4][8][4];
        #pragma unroll
        for (int i = 0; i < 4; i++)
            #pragma unroll
            for (int nt = 0; nt < 8; nt++)
                #pragma unroll
                for (int c = 0; c < 4; c++) acc[i][nt][c] = 0.f;

        #pragma unroll 1
        for (int s = 0; s < 8; s++) {
            const uint32_t ks = s * 32;
            unsigned aB[4][4], aS[4][4];
            #pragma unroll
            for (int i = 0; i < 4; i++) {
                LDSM_X4(aB[i], aAddr[i] + ks);
                LDSM_X4(aS[i], aAddr[i] + ks + A_SMALL_OFF);
            }
            #pragma unroll
            for (int j = 0; j < 4; j++) {
                unsigned bBf[4], bSf[4];
                LDSM_X4(bBf, bAddr[j] + ks);
                LDSM_X4(bSf, bAddr[j] + ks + B_SMALL_OFF);
                #pragma unroll
                for (int i = 0; i < 4; i++) {
                    mma_bf16(acc[i][2 * j],     aB[i], bBf[0], bBf[1]);
                    mma_bf16(acc[i][2 * j],     aB[i], bSf[0], bSf[1]);
                    mma_bf16(acc[i][2 * j],     aS[i], bBf[0], bBf[1]);
                    mma_bf16(acc[i][2 * j + 1], aB[i], bBf[2], bBf[3]);
                    mma_bf16(acc[i][2 * j + 1], aB[i], bSf[2], bSf[3]);
                    mma_bf16(acc[i][2 * j + 1], aS[i], bBf[2], bBf[3]);
                }
            }
        }

        // epilogue: relu(+bias), mean over 16 edge rows, write out
        #pragma unroll
        for (int i = 0; i < 4; i++) {
            const int point = s_pts[pg * 4 + i];
            float* orow = out + (size_t)point * (Oq + 1);
            #pragma unroll
            for (int nt = 0; nt < 8; nt++) {
                float s0 = fmaxf(acc[i][nt][0] + bias[nt][0], 0.f)
                         + fmaxf(acc[i][nt][2] + bias[nt][0], 0.f);
                float s1 = fmaxf(acc[i][nt][1] + bias[nt][1], 0.f)
                         + fmaxf(acc[i][nt][3] + bias[nt][1], 0.f);
                #pragma unroll
                for (int o = 4; o < 32; o <<= 1) {
                    s0 += __shfl_xor_sync(0xffffffffu, s0, o);
                    s1 += __shfl_xor_sync(0xffffffffu, s1, o);
                }
                if ((lane >> 2) == 0) {
                    orow[n0 + nt * 8 + 2 * t4]     = s0 * (1.f / 16.f);
                    orow[n0 + nt * 8 + 2 * t4 + 1] = s1 * (1.f / 16.f);
                }
            }
            if (nch == 0 && lane == 0) orow[Oq] = 1.f;
        }
        __syncthreads();   // fragment reads done before next group's build
    }
}

// ---------------------------------------------------------------------------
extern "C" void kernel_launch(void* const* d_in, const int* in_sizes, int n_in,
                              void* d_out, int out_size) {
    (void)in_sizes; (void)n_in; (void)out_size;
    const float* x  = (const float*)d_in[0];
    const float* W1 = (const float*)d_in[1];
    const float* b1 = (const float*)d_in[2];
    const float* W2 = (const float*)d_in[3];
    const float* b2 = (const float*)d_in[4];
    float* out = (float*)d_out;

    const int smem = B_BASE_OFF + 2 * (Oq * LDH * 2);   // 69632 + 139264 = 208896
    cudaFuncSetAttribute(mlp_kernel, cudaFuncAttributeMaxDynamicSharedMemorySize, smem);

    prep_kernel<<<256, 128>>>(W2);
    zero_kernel<<<2048, 256>>>((float4*)out, Bq * Pq * (Oq + 1) / 4);
    knn_kernel<<<dim3(Bq, 2), 64>>>(x);
    embed_kernel<<<Bq * Pq, Hq>>>(x, W1, b1);
    list_kernel<<<(Bq * Pq + 255) / 256, 256>>>(x);
    mlp_kernel<<<148, 256, smem>>>(b2, out);
}

// round 11
// speedup vs baseline: 2.6390x; 1.4274x over previous
#include <cuda_runtime.h>
#include <cuda_fp16.h>
#include <cstdint>

#define Bq 256
#define Pq 128
#define Kq 16
#define Hq 128
#define Oq 256
#define LDH 136            // padded row stride (elements); 272 bytes

__device__ int   g_idx [Bq*Pq*Kq];
__device__ float g_base[Bq*Pq*Hq];
__device__ float g_y   [Bq*Pq*Hq];
__device__ __align__(16) __half g_wH[Oq*LDH];   // W2^T fp16 [n][k]
__device__ int g_cnt;
__device__ int g_list[Bq*Pq];

// ---------------- K1: exact KNN (top-17, ties->lower idx, drop self) -------
__global__ __launch_bounds__(64) void knn_kernel(const float* __restrict__ x) {
    const int b = blockIdx.x, half = blockIdx.y, t = threadIdx.x;
    __shared__ float scx[Pq], scy[Pq], sval[Pq];
    __shared__ float sdist[Pq * 64];
    for (int j = t; j < Pq; j += 64) {
        const float* row = x + ((size_t)b * Pq + j) * 10;
        scx[j] = row[0]; scy[j] = row[1]; sval[j] = row[9];
    }
    __syncthreads();
    const int p = half * 64 + t;
    if (sval[p] <= 0.f) return;
    const float cx = scx[p], cy = scy[p];
    for (int j = 0; j < Pq; j++) {
        float dx = scx[j] - cx, dy = scy[j] - cy;
        float d = dx * dx + dy * dy;
        if (sval[j] <= 0.f) d = 1e9f;
        sdist[j * 64 + t] = d;
    }
    const int off = (b * Pq + p) * Kq;
    #pragma unroll 1
    for (int pass = 0; pass < Kq + 1; pass++) {
        float best = 3.0e38f; int bj = 0;
        for (int j = 0; j < Pq; j++) {
            float d = sdist[j * 64 + t];
            if (d < best) { best = d; bj = j; }
        }
        sdist[bj * 64 + t] = 3.4e38f;
        if (pass >= 1) g_idx[off + pass - 1] = bj;
    }
}

// ---------------- K2: layer-1 factorization --------------------------------
__global__ __launch_bounds__(128) void embed_kernel(const float* __restrict__ x,
                                                    const float* __restrict__ W1,
                                                    const float* __restrict__ b1) {
    const int bp = blockIdx.x, h = threadIdx.x;
    const float* row = x + (size_t)bp * 10;
    float base = b1[h], y = 0.f;
    #pragma unroll
    for (int e = 0; e < 9; e++) {
        float v = row[e];
        float wa = W1[e * Hq + h], wb = W1[(e + 9) * Hq + h];
        base = fmaf(v, wa - wb, base);
        y    = fmaf(v, wb, y);
    }
    g_base[(size_t)bp * Hq + h] = base;
    g_y   [(size_t)bp * Hq + h] = y;
}

// ---------------- prep: W2 -> fp16, transposed [n][k] + pad ----------------
__global__ __launch_bounds__(128) void prep_kernel(const float* __restrict__ W2) {
    const int i = blockIdx.x * 128 + threadIdx.x;   // i = k*256 + n
    if (i == 0) g_cnt = 0;
    g_list[i] = 0;                                  // pad slots -> point 0 (always live)
    const int k = i >> 8, n = i & 255;
    g_wH[n * LDH + k] = __float2half_rn(W2[i]);
}

// ---------------- zero output + live list ----------------------------------
__global__ void zero_kernel(float4* __restrict__ o, int n4) {
    int i = blockIdx.x * blockDim.x + threadIdx.x;
    const int stride = gridDim.x * blockDim.x;
    const float4 z = make_float4(0.f, 0.f, 0.f, 0.f);
    for (; i < n4; i += stride) o[i] = z;
}
__global__ __launch_bounds__(256) void list_kernel(const float* __restrict__ x) {
    const int p = blockIdx.x * 256 + threadIdx.x;
    if (p >= Bq * Pq) return;
    if (x[(size_t)p * 10 + 9] > 0.f) { int s = atomicAdd(&g_cnt, 1); g_list[s] = p; }
}

// ---------------- helpers --------------------------------------------------
__device__ __forceinline__ uint32_t smem_u32(const void* p) {
    uint32_t a;
    asm("{ .reg .u64 t; cvta.to.shared.u64 t, %1; cvt.u32.u64 %0, t; }" : "=r"(a) : "l"(p));
    return a;
}
__device__ __forceinline__ void mma_f16(float* d, const unsigned* a,
                                        unsigned b0, unsigned b1) {
    asm volatile(
        "mma.sync.aligned.m16n8k16.row.col.f32.f16.f16.f32 "
        "{%0,%1,%2,%3},{%4,%5,%6,%7},{%8,%9},{%0,%1,%2,%3};"
        : "+f"(d[0]), "+f"(d[1]), "+f"(d[2]), "+f"(d[3])
        : "r"(a[0]), "r"(a[1]), "r"(a[2]), "r"(a[3]), "r"(b0), "r"(b1));
}
#define LDSM_X4(r, addr) \
    asm volatile("ldmatrix.sync.aligned.m8n8.x4.shared.b16 {%0,%1,%2,%3}, [%4];" \
        : "=r"((r)[0]), "=r"((r)[1]), "=r"((r)[2]), "=r"((r)[3]) : "r"(addr))

#define B_BASE_OFF 34816u   // A tile = 128*272 bytes

// ---------------- K3: persistent mma.sync fp16 MLP -------------------------
__global__ __launch_bounds__(256, 1) void mlp_kernel(const float* __restrict__ b2,
                                                     float* __restrict__ out) {
    extern __shared__ __align__(16) char dyn[];
    __shared__ int s_pts[8];

    const int tid = threadIdx.x, warp = tid >> 5, lane = tid & 31;
    const int t4 = lane & 3;
    const int pg = warp >> 2, nch = warp & 3, n0 = nch * 64;
    const uint32_t sbase = smem_u32(dyn);

    {   // stage fp16 W2^T once per block (linear copy, layout preserved)
        const float4* sW = (const float4*)g_wH;
        float4* dW = (float4*)(dyn + B_BASE_OFF);
        for (int j = tid; j < Oq * LDH / 8; j += 256) dW[j] = sW[j];
    }

    // per-lane ldmatrix base addresses (identical mapping to validated R10)
    uint32_t aAddr[4];
    #pragma unroll
    for (int i = 0; i < 4; i++)
        aAddr[i] = sbase + ((pg * 4 + i) * 16 + (lane & 15)) * 272 + (lane >> 4) * 16;
    uint32_t bAddr[4];
    #pragma unroll
    for (int j = 0; j < 4; j++)
        bAddr[j] = sbase + B_BASE_OFF +
                   (n0 + j * 16 + (lane & 7) + ((lane >> 4) << 3)) * 272 +
                   ((lane >> 3) & 1) * 16;

    float bias[8][2];
    #pragma unroll
    for (int nt = 0; nt < 8; nt++) {
        bias[nt][0] = b2[n0 + nt * 8 + 2 * t4];
        bias[nt][1] = b2[n0 + nt * 8 + 2 * t4 + 1];
    }
    __syncthreads();

    const int cnt = g_cnt, ngrp = (cnt + 7) >> 3;
    for (int grp = blockIdx.x; grp < ngrp; grp += gridDim.x) {
        if (tid < 8) s_pts[tid] = g_list[grp * 8 + tid];
        __syncthreads();

        {   // h1 = relu(base + y[nbr]) -> fp16 rows (stride 272B)
            const int row = tid >> 1, half = tid & 1;
            const int point = s_pts[tid >> 5], m = row & 15;
            const int nb = g_idx[point * Kq + m];
            const int bat = point >> 7;
            const float4* yv = (const float4*)(g_y + (size_t)(bat * Pq + nb) * Hq) + half * 16;
            const float4* bv = (const float4*)(g_base + (size_t)point * Hq) + half * 16;
            char* pA = dyn + row * 272 + half * 128;
            #pragma unroll
            for (int c = 0; c < 8; c++) {
                float4 ya = yv[2 * c],     ba  = bv[2 * c];
                float4 yb = yv[2 * c + 1], bbv = bv[2 * c + 1];
                __half2 h0, h1, h2, h3;
                h0.x = __float2half_rn(fmaxf(ba.x + ya.x, 0.f));
                h0.y = __float2half_rn(fmaxf(ba.y + ya.y, 0.f));
                h1.x = __float2half_rn(fmaxf(ba.z + ya.z, 0.f));
                h1.y = __float2half_rn(fmaxf(ba.w + ya.w, 0.f));
                h2.x = __float2half_rn(fmaxf(bbv.x + yb.x, 0.f));
                h2.y = __float2half_rn(fmaxf(bbv.y + yb.y, 0.f));
                h3.x = __float2half_rn(fmaxf(bbv.z + yb.z, 0.f));
                h3.y = __float2half_rn(fmaxf(bbv.w + yb.w, 0.f));
                uint4 q;
                q.x = *(uint32_t*)&h0; q.y = *(uint32_t*)&h1;
                q.z = *(uint32_t*)&h2; q.w = *(uint32_t*)&h3;
                *(uint4*)(pA + 16 * c) = q;
            }
        }
        __syncthreads();

        float acc[4][8][4];
        #pragma unroll
        for (int i = 0; i < 4; i++)
            #pragma unroll
            for (int nt = 0; nt < 8; nt++)
                #pragma unroll
                for (int c = 0; c < 4; c++) acc[i][nt][c] = 0.f;

        #pragma unroll 1
        for (int s = 0; s < 8; s++) {
            const uint32_t ks = s * 32;
            unsigned aF[4][4];
            #pragma unroll
            for (int i = 0; i < 4; i++) LDSM_X4(aF[i], aAddr[i] + ks);
            #pragma unroll
            for (int j = 0; j < 4; j++) {
                unsigned bF[4];
                LDSM_X4(bF, bAddr[j] + ks);
                #pragma unroll
                for (int i = 0; i < 4; i++) {
                    mma_f16(acc[i][2 * j],     aF[i], bF[0], bF[1]);
                    mma_f16(acc[i][2 * j + 1], aF[i], bF[2], bF[3]);
                }
            }
        }

        // epilogue: relu(+bias), mean over 16 edge rows, write out
        #pragma unroll
        for (int i = 0; i < 4; i++) {
            const int point = s_pts[pg * 4 + i];
            float* orow = out + (size_t)point * (Oq + 1);
            #pragma unroll
            for (int nt = 0; nt < 8; nt++) {
                float s0 = fmaxf(acc[i][nt][0] + bias[nt][0], 0.f)
                         + fmaxf(acc[i][nt][2] + bias[nt][0], 0.f);
                float s1 = fmaxf(acc[i][nt][1] + bias[nt][1], 0.f)
                         + fmaxf(acc[i][nt][3] + bias[nt][1], 0.f);
                #pragma unroll
                for (int o = 4; o < 32; o <<= 1) {
                    s0 += __shfl_xor_sync(0xffffffffu, s0, o);
                    s1 += __shfl_xor_sync(0xffffffffu, s1, o);
                }
                if ((lane >> 2) == 0) {
                    orow[n0 + nt * 8 + 2 * t4]     = s0 * (1.f / 16.f);
                    orow[n0 + nt * 8 + 2 * t4 + 1] = s1 * (1.f / 16.f);
                }
            }
            if (nch == 0 && lane == 0) orow[Oq] = 1.f;
        }
        __syncthreads();   // fragment reads done before next group's build
    }
}

// ---------------------------------------------------------------------------
extern "C" void kernel_launch(void* const* d_in, const int* in_sizes, int n_in,
                              void* d_out, int out_size) {
    (void)in_sizes; (void)n_in; (void)out_size;
    const float* x  = (const float*)d_in[0];
    const float* W1 = (const float*)d_in[1];
    const float* b1 = (const float*)d_in[2];
    const float* W2 = (const float*)d_in[3];
    const float* b2 = (const float*)d_in[4];
    float* out = (float*)d_out;

    const int smem = B_BASE_OFF + Oq * LDH * 2;   // 34816 + 69632 = 104448
    cudaFuncSetAttribute(mlp_kernel, cudaFuncAttributeMaxDynamicSharedMemorySize, smem);

    prep_kernel<<<256, 128>>>(W2);
    zero_kernel<<<2048, 256>>>((float4*)out, Bq * Pq * (Oq + 1) / 4);
    knn_kernel<<<dim3(Bq, 2), 64>>>(x);
    embed_kernel<<<Bq * Pq, Hq>>>(x, W1, b1);
    list_kernel<<<(Bq * Pq + 255) / 256, 256>>>(x);
    mlp_kernel<<<148, 256, smem>>>(b2, out);
}

// round 12
// speedup vs baseline: 2.6922x; 1.0202x over previous
#include <cuda_runtime.h>
#include <cuda_fp16.h>
#include <cstdint>

#define Bq 256
#define Pq 128
#define Kq 16
#define Hq 128
#define Oq 256
#define LDH 136            // padded row stride (elements); 272 bytes

__device__ int   g_idx [Bq*Pq*Kq];
__device__ float g_base[Bq*Pq*Hq];
__device__ float g_y   [Bq*Pq*Hq];
__device__ __align__(16) __half g_wH[Oq*LDH];   // W2^T fp16 [n][k]
__device__ int g_cnt;
__device__ int g_list[Bq*Pq];

// ---------------- K1: exact KNN (top-17, ties->lower idx, drop self) -------
__global__ __launch_bounds__(64) void knn_kernel(const float* __restrict__ x) {
    const int b = blockIdx.x, half = blockIdx.y, t = threadIdx.x;
    __shared__ float scx[Pq], scy[Pq], sval[Pq];
    __shared__ float sdist[Pq * 64];
    for (int j = t; j < Pq; j += 64) {
        const float* row = x + ((size_t)b * Pq + j) * 10;
        scx[j] = row[0]; scy[j] = row[1]; sval[j] = row[9];
    }
    __syncthreads();
    const int p = half * 64 + t;
    if (sval[p] <= 0.f) return;
    const float cx = scx[p], cy = scy[p];
    for (int j = 0; j < Pq; j++) {
        float dx = scx[j] - cx, dy = scy[j] - cy;
        float d = dx * dx + dy * dy;
        if (sval[j] <= 0.f) d = 1e9f;
        sdist[j * 64 + t] = d;
    }
    const int off = (b * Pq + p) * Kq;
    #pragma unroll 1
    for (int pass = 0; pass < Kq + 1; pass++) {
        float best = 3.0e38f; int bj = 0;
        for (int j = 0; j < Pq; j++) {
            float d = sdist[j * 64 + t];
            if (d < best) { best = d; bj = j; }
        }
        sdist[bj * 64 + t] = 3.4e38f;
        if (pass >= 1) g_idx[off + pass - 1] = bj;
    }
}

// ---------------- K2: layer-1 factorization, 16 pts/block, W1 in regs ------
// also builds the live-point list (fused old list_kernel)
__global__ __launch_bounds__(128) void embed_kernel(const float* __restrict__ x,
                                                    const float* __restrict__ W1,
                                                    const float* __restrict__ b1) {
    const int h  = threadIdx.x;
    const int p0 = blockIdx.x * 16;
    float wa[9], wb[9];
    #pragma unroll
    for (int e = 0; e < 9; e++) {
        float a = W1[e * Hq + h], b = W1[(e + 9) * Hq + h];
        wa[e] = a - b; wb[e] = b;
    }
    const float bb = b1[h];
    #pragma unroll 1
    for (int q = 0; q < 16; q++) {
        const int bp = p0 + q;
        const float* row = x + (size_t)bp * 10;
        float base = bb, y = 0.f;
        #pragma unroll
        for (int e = 0; e < 9; e++) {
            float v = row[e];
            base = fmaf(v, wa[e], base);
            y    = fmaf(v, wb[e], y);
        }
        g_base[(size_t)bp * Hq + h] = base;
        g_y   [(size_t)bp * Hq + h] = y;
        if (h == 0 && row[9] > 0.f) {
            int s = atomicAdd(&g_cnt, 1);
            g_list[s] = bp;
        }
    }
}

// ---------------- prep: W2 -> fp16, transposed [n][k] + pad; reset list ----
__global__ __launch_bounds__(128) void prep_kernel(const float* __restrict__ W2) {
    const int i = blockIdx.x * 128 + threadIdx.x;   // i = k*256 + n
    if (i == 0) g_cnt = 0;
    g_list[i] = 0;                                  // pad slots -> point 0 (always live)
    const int k = i >> 8, n = i & 255;
    g_wH[n * LDH + k] = __float2half_rn(W2[i]);
}

// ---------------- zero output ----------------------------------------------
__global__ void zero_kernel(float4* __restrict__ o, int n4) {
    int i = blockIdx.x * blockDim.x + threadIdx.x;
    const int stride = gridDim.x * blockDim.x;
    const float4 z = make_float4(0.f, 0.f, 0.f, 0.f);
    for (; i < n4; i += stride) o[i] = z;
}

// ---------------- helpers --------------------------------------------------
__device__ __forceinline__ uint32_t smem_u32(const void* p) {
    uint32_t a;
    asm("{ .reg .u64 t; cvta.to.shared.u64 t, %1; cvt.u32.u64 %0, t; }" : "=r"(a) : "l"(p));
    return a;
}
__device__ __forceinline__ void mma_f16(float* d, const unsigned* a,
                                        unsigned b0, unsigned b1) {
    asm volatile(
        "mma.sync.aligned.m16n8k16.row.col.f32.f16.f16.f32 "
        "{%0,%1,%2,%3},{%4,%5,%6,%7},{%8,%9},{%0,%1,%2,%3};"
        : "+f"(d[0]), "+f"(d[1]), "+f"(d[2]), "+f"(d[3])
        : "r"(a[0]), "r"(a[1]), "r"(a[2]), "r"(a[3]), "r"(b0), "r"(b1));
}
#define LDSM_X4(r, addr) \
    asm volatile("ldmatrix.sync.aligned.m8n8.x4.shared.b16 {%0,%1,%2,%3}, [%4];" \
        : "=r"((r)[0]), "=r"((r)[1]), "=r"((r)[2]), "=r"((r)[3]) : "r"(addr))
#define BAR_HALF(id) \
    asm volatile("bar.sync %0, 128;" :: "r"(id) : "memory")

#define B_BASE_OFF 34816u   // A tile = 128*272 bytes

// ---------------- K3: persistent mma.sync fp16 MLP, split-half barriers ----
__global__ __launch_bounds__(256, 1) void mlp_kernel(const float* __restrict__ b2,
                                                     float* __restrict__ out) {
    extern __shared__ __align__(16) char dyn[];
    __shared__ int s_pts[8];

    const int tid = threadIdx.x, warp = tid >> 5, lane = tid & 31;
    const int t4 = lane & 3;
    const int pg = warp >> 2, nch = warp & 3, n0 = nch * 64;
    const int barid = 1 + pg;                    // per-half named barrier
    const uint32_t sbase = smem_u32(dyn);

    {   // stage fp16 W2^T once per block (linear copy, layout preserved)
        const float4* sW = (const float4*)g_wH;
        float4* dW = (float4*)(dyn + B_BASE_OFF);
        for (int j = tid; j < Oq * LDH / 8; j += 256) dW[j] = sW[j];
    }

    // per-lane ldmatrix base addresses (identical mapping to validated R10/R11)
    uint32_t aAddr[4];
    #pragma unroll
    for (int i = 0; i < 4; i++)
        aAddr[i] = sbase + ((pg * 4 + i) * 16 + (lane & 15)) * 272 + (lane >> 4) * 16;
    uint32_t bAddr[4];
    #pragma unroll
    for (int j = 0; j < 4; j++)
        bAddr[j] = sbase + B_BASE_OFF +
                   (n0 + j * 16 + (lane & 7) + ((lane >> 4) << 3)) * 272 +
                   ((lane >> 3) & 1) * 16;

    float bias[8][2];
    #pragma unroll
    for (int nt = 0; nt < 8; nt++) {
        bias[nt][0] = b2[n0 + nt * 8 + 2 * t4];
        bias[nt][1] = b2[n0 + nt * 8 + 2 * t4 + 1];
    }
    __syncthreads();                             // staging complete (full block)

    const int cnt = g_cnt, ngrp = (cnt + 7) >> 3;
    for (int grp = blockIdx.x; grp < ngrp; grp += gridDim.x) {
        // each half loads its own 4 points
        if (nch == 0 && lane < 4) s_pts[pg * 4 + lane] = g_list[grp * 8 + pg * 4 + lane];
        BAR_HALF(barid);

        {   // h1 = relu(base + y[nbr]) -> fp16 rows (half h builds rows 64h..64h+63)
            const int row = tid >> 1, half = tid & 1;
            const int point = s_pts[tid >> 5], m = row & 15;
            const int nb = g_idx[point * Kq + m];
            const int bat = point >> 7;
            const float4* yv = (const float4*)(g_y + (size_t)(bat * Pq + nb) * Hq) + half * 16;
            const float4* bv = (const float4*)(g_base + (size_t)point * Hq) + half * 16;
            char* pA = dyn + row * 272 + half * 128;
            #pragma unroll
            for (int c = 0; c < 8; c++) {
                float4 ya = yv[2 * c],     ba  = bv[2 * c];
                float4 yb = yv[2 * c + 1], bbv = bv[2 * c + 1];
                __half2 h0, h1, h2, h3;
                h0.x = __float2half_rn(fmaxf(ba.x + ya.x, 0.f));
                h0.y = __float2half_rn(fmaxf(ba.y + ya.y, 0.f));
                h1.x = __float2half_rn(fmaxf(ba.z + ya.z, 0.f));
                h1.y = __float2half_rn(fmaxf(ba.w + ya.w, 0.f));
                h2.x = __float2half_rn(fmaxf(bbv.x + yb.x, 0.f));
                h2.y = __float2half_rn(fmaxf(bbv.y + yb.y, 0.f));
                h3.x = __float2half_rn(fmaxf(bbv.z + yb.z, 0.f));
                h3.y = __float2half_rn(fmaxf(bbv.w + yb.w, 0.f));
                uint4 q;
                q.x = *(uint32_t*)&h0; q.y = *(uint32_t*)&h1;
                q.z = *(uint32_t*)&h2; q.w = *(uint32_t*)&h3;
                *(uint4*)(pA + 16 * c) = q;
            }
        }
        BAR_HALF(barid);                          // this half's A rows ready

        float acc[4][8][4];
        #pragma unroll
        for (int i = 0; i < 4; i++)
            #pragma unroll
            for (int nt = 0; nt < 8; nt++)
                #pragma unroll
                for (int c = 0; c < 4; c++) acc[i][nt][c] = 0.f;

        #pragma unroll 1
        for (int s = 0; s < 8; s++) {
            const uint32_t ks = s * 32;
            unsigned aF[4][4];
            #pragma unroll
            for (int i = 0; i < 4; i++) LDSM_X4(aF[i], aAddr[i] + ks);
            #pragma unroll
            for (int j = 0; j < 4; j++) {
                unsigned bF[4];
                LDSM_X4(bF, bAddr[j] + ks);
                #pragma unroll
                for (int i = 0; i < 4; i++) {
                    mma_f16(acc[i][2 * j],     aF[i], bF[0], bF[1]);
                    mma_f16(acc[i][2 * j + 1], aF[i], bF[2], bF[3]);
                }
            }
        }

        // epilogue: relu(+bias), mean over 16 edge rows, write out
        #pragma unroll
        for (int i = 0; i < 4; i++) {
            const int point = s_pts[pg * 4 + i];
            float* orow = out + (size_t)point * (Oq + 1);
            #pragma unroll
            for (int nt = 0; nt < 8; nt++) {
                float s0 = fmaxf(acc[i][nt][0] + bias[nt][0], 0.f)
                         + fmaxf(acc[i][nt][2] + bias[nt][0], 0.f);
                float s1 = fmaxf(acc[i][nt][1] + bias[nt][1], 0.f)
                         + fmaxf(acc[i][nt][3] + bias[nt][1], 0.f);
                #pragma unroll
                for (int o = 4; o < 32; o <<= 1) {
                    s0 += __shfl_xor_sync(0xffffffffu, s0, o);
                    s1 += __shfl_xor_sync(0xffffffffu, s1, o);
                }
                if ((lane >> 2) == 0) {
                    orow[n0 + nt * 8 + 2 * t4]     = s0 * (1.f / 16.f);
                    orow[n0 + nt * 8 + 2 * t4 + 1] = s1 * (1.f / 16.f);
                }
            }
            if (nch == 0 && lane == 0) orow[Oq] = 1.f;
        }
        BAR_HALF(barid);   // this half's fragment reads done before next build
    }
}

// ---------------------------------------------------------------------------
extern "C" void kernel_launch(void* const* d_in, const int* in_sizes, int n_in,
                              void* d_out, int out_size) {
    (void)in_sizes; (void)n_in; (void)out_size;
    const float* x  = (const float*)d_in[0];
    const float* W1 = (const float*)d_in[1];
    const float* b1 = (const float*)d_in[2];
    const float* W2 = (const float*)d_in[3];
    const float* b2 = (const float*)d_in[4];
    float* out = (float*)d_out;

    const int smem = B_BASE_OFF + Oq * LDH * 2;   // 34816 + 69632 = 104448
    cudaFuncSetAttribute(mlp_kernel, cudaFuncAttributeMaxDynamicSharedMemorySize, smem);

    prep_kernel<<<256, 128>>>(W2);                // resets g_cnt (before embed's atomics)
    zero_kernel<<<2048, 256>>>((float4*)out, Bq * Pq * (Oq + 1) / 4);
    knn_kernel<<<dim3(Bq, 2), 64>>>(x);
    embed_kernel<<<Bq * Pq / 16, Hq>>>(x, W1, b1);
    mlp_kernel<<<148, 256, smem>>>(b2, out);
}

// round 13
// speedup vs baseline: 2.9807x; 1.1072x over previous
#include <cuda_runtime.h>
#include <cuda_fp16.h>
#include <cstdint>

#define Bq 256
#define Pq 128
#define Kq 16
#define Hq 128
#define Oq 256
#define LDH 136            // padded A/B row stride (elements); 272 bytes

__device__ int   g_idx [Bq*Pq*Kq];
__device__ float g_base[Bq*Pq*Hq];
__device__ float g_y   [Bq*Pq*Hq];
__device__ __align__(16) __half g_wH[Oq*LDH];   // W2^T fp16 [n][k]
__device__ int g_cnt;
__device__ int g_list[Bq*Pq];

// ---------------- K1: exact KNN (top-17, ties->lower idx, drop self) -------
__global__ __launch_bounds__(64) void knn_kernel(const float* __restrict__ x) {
    const int b = blockIdx.x, half = blockIdx.y, t = threadIdx.x;
    __shared__ float scx[Pq], scy[Pq], sval[Pq];
    __shared__ float sdist[Pq * 64];
    for (int j = t; j < Pq; j += 64) {
        const float* row = x + ((size_t)b * Pq + j) * 10;
        scx[j] = row[0]; scy[j] = row[1]; sval[j] = row[9];
    }
    __syncthreads();
    const int p = half * 64 + t;
    if (sval[p] <= 0.f) return;
    const float cx = scx[p], cy = scy[p];
    for (int j = 0; j < Pq; j++) {
        float dx = scx[j] - cx, dy = scy[j] - cy;
        float d = dx * dx + dy * dy;
        if (sval[j] <= 0.f) d = 1e9f;
        sdist[j * 64 + t] = d;
    }
    const int off = (b * Pq + p) * Kq;
    #pragma unroll 1
    for (int pass = 0; pass < Kq + 1; pass++) {
        float best = 3.0e38f; int bj = 0;
        for (int j = 0; j < Pq; j++) {
            float d = sdist[j * 64 + t];
            if (d < best) { best = d; bj = j; }
        }
        sdist[bj * 64 + t] = 3.4e38f;
        if (pass >= 1) g_idx[off + pass - 1] = bj;
    }
}

// ---------------- K2: layer-1 factorization; x staged in smem; list fused --
// 256 thr = 2 h-groups x 128; 16 points/block, 8 per h-group.
__global__ __launch_bounds__(256) void embed_kernel(const float* __restrict__ x,
                                                    const float* __restrict__ W1,
                                                    const float* __restrict__ b1) {
    __shared__ float sx[16][10];
    const int tid = threadIdx.x;
    const int h = tid & 127, gsel = tid >> 7;
    const int p0 = blockIdx.x * 16;

    for (int i = tid; i < 160; i += 256) sx[i / 10][i % 10] = x[(size_t)p0 * 10 + i];
    float wa[9], wb[9];
    #pragma unroll
    for (int e = 0; e < 9; e++) {
        float a = W1[e * Hq + h], b = W1[(e + 9) * Hq + h];
        wa[e] = a - b; wb[e] = b;
    }
    const float bb = b1[h];
    __syncthreads();

    if (tid < 16 && sx[tid][9] > 0.f) {
        int s = atomicAdd(&g_cnt, 1);
        g_list[s] = p0 + tid;
    }
    #pragma unroll
    for (int q = 0; q < 8; q++) {
        const int lp = gsel * 8 + q;
        const int bp = p0 + lp;
        float base = bb, y = 0.f;
        #pragma unroll
        for (int e = 0; e < 9; e++) {
            float v = sx[lp][e];
            base = fmaf(v, wa[e], base);
            y    = fmaf(v, wb[e], y);
        }
        g_base[(size_t)bp * Hq + h] = base;
        g_y   [(size_t)bp * Hq + h] = y;
    }
}

// ---------------- prep: W2 -> fp16, transposed [n][k] + pad; reset list ----
__global__ __launch_bounds__(128) void prep_kernel(const float* __restrict__ W2) {
    const int i = blockIdx.x * 128 + threadIdx.x;   // i = k*256 + n
    if (i == 0) g_cnt = 0;
    g_list[i] = 0;                                  // pad slots -> point 0 (always live)
    const int k = i >> 8, n = i & 255;
    g_wH[n * LDH + k] = __float2half_rn(W2[i]);
}

// ---------------- zero dead output rows only (warp per point) --------------
__global__ __launch_bounds__(256) void zero_kernel(const float* __restrict__ x,
                                                   float* __restrict__ out) {
    const int p = blockIdx.x * 8 + (threadIdx.x >> 5);
    const int l = threadIdx.x & 31;
    if (x[(size_t)p * 10 + 9] > 0.f) return;        // live rows written by mlp
    float* orow = out + (size_t)p * (Oq + 1);
    for (int j = l; j < Oq + 1; j += 32) orow[j] = 0.f;
}

// ---------------- helpers --------------------------------------------------
__device__ __forceinline__ uint32_t smem_u32(const void* p) {
    uint32_t a;
    asm("{ .reg .u64 t; cvta.to.shared.u64 t, %1; cvt.u32.u64 %0, t; }" : "=r"(a) : "l"(p));
    return a;
}
__device__ __forceinline__ void mma_f16(float* d, const unsigned* a,
                                        unsigned b0, unsigned b1) {
    asm volatile(
        "mma.sync.aligned.m16n8k16.row.col.f32.f16.f16.f32 "
        "{%0,%1,%2,%3},{%4,%5,%6,%7},{%8,%9},{%0,%1,%2,%3};"
        : "+f"(d[0]), "+f"(d[1]), "+f"(d[2]), "+f"(d[3])
        : "r"(a[0]), "r"(a[1]), "r"(a[2]), "r"(a[3]), "r"(b0), "r"(b1));
}
#define LDSM_X4(r, addr) \
    asm volatile("ldmatrix.sync.aligned.m8n8.x4.shared.b16 {%0,%1,%2,%3}, [%4];" \
        : "=r"((r)[0]), "=r"((r)[1]), "=r"((r)[2]), "=r"((r)[3]) : "r"(addr))
#define CP_ASYNC16(dst, src) \
    asm volatile("cp.async.cg.shared.global [%0], [%1], 16;" :: "r"(dst), "l"(src))
#define CP_COMMIT()  asm volatile("cp.async.commit_group;" ::: "memory")
#define CP_WAIT0()   asm volatile("cp.async.wait_group 0;"  ::: "memory")

#define B_BASE_OFF 34816u                 // A tile = 128*272 bytes
#define YST_OFF    104448u                // + B tile 69632
#define BST_OFF    172032u                // + y staging 128*528
#define SMEM_TOT   176256u                // + base staging 8*528

// ---------------- K3: persistent fp16 MLP with cp.async pipeline -----------
__global__ __launch_bounds__(256, 1) void mlp_kernel(const float* __restrict__ b2,
                                                     float* __restrict__ out) {
    extern __shared__ __align__(16) char dyn[];
    __shared__ int s_pts[2][8];

    const int tid = threadIdx.x, warp = tid >> 5, lane = tid & 31;
    const int t4 = lane & 3;
    const int pg = warp >> 2, nch = warp & 3, n0 = nch * 64;
    const uint32_t sbase = smem_u32(dyn);

    {   // stage fp16 W2^T once per block
        const float4* sW = (const float4*)g_wH;
        float4* dW = (float4*)(dyn + B_BASE_OFF);
        for (int j = tid; j < Oq * LDH / 8; j += 256) dW[j] = sW[j];
    }

    // ldmatrix base addresses (identical mapping to validated R10-R12)
    uint32_t aAddr[4];
    #pragma unroll
    for (int i = 0; i < 4; i++)
        aAddr[i] = sbase + ((pg * 4 + i) * 16 + (lane & 15)) * 272 + (lane >> 4) * 16;
    uint32_t bAddr[4];
    #pragma unroll
    for (int j = 0; j < 4; j++)
        bAddr[j] = sbase + B_BASE_OFF +
                   (n0 + j * 16 + (lane & 7) + ((lane >> 4) << 3)) * 272 +
                   ((lane >> 3) & 1) * 16;

    float bias[8][2];
    #pragma unroll
    for (int nt = 0; nt < 8; nt++) {
        bias[nt][0] = b2[n0 + nt * 8 + 2 * t4];
        bias[nt][1] = b2[n0 + nt * 8 + 2 * t4 + 1];
    }

    // staging-thread mapping: r = A row, hf = which 64-col half
    const int r = tid & 127, hf = tid >> 7;
    const uint32_t yDst = sbase + YST_OFF + r * 528 + hf * 256;
    const uint32_t bDst = sbase + BST_OFF + (tid >> 5) * 528 + (tid & 31) * 16;

    const int cnt = g_cnt, ngrp = (cnt + 7) >> 3, stride = gridDim.x;
    int grp = blockIdx.x;
    if (tid < 8 && grp < ngrp) s_pts[0][tid] = g_list[grp * 8 + tid];
    __syncthreads();    // W2 staged + s_pts[0] visible

    if (grp < ngrp) {   // prologue prefetch for first group
        const int point = s_pts[0][r >> 4];
        const int nb = g_idx[point * Kq + (r & 15)];
        const char* src = (const char*)(g_y + (size_t)((point >> 7) * Pq + nb) * Hq) + hf * 256;
        #pragma unroll
        for (int j = 0; j < 16; j++) CP_ASYNC16(yDst + 16 * j, src + 16 * j);
        const char* bsrc = (const char*)(g_base + (size_t)s_pts[0][tid >> 5] * Hq) + (tid & 31) * 16;
        CP_ASYNC16(bDst, bsrc);
    }
    CP_COMMIT();

    int par = 0;
    for (; grp < ngrp; grp += stride) {
        const int nxt = grp + stride;
        CP_WAIT0();
        __syncthreads();    // staging arrived; prev group's MMA/epilogue done

        {   // convert staging -> fp16 A tile (pure smem, conflict-free)
            const char* yS = dyn + YST_OFF + r * 528 + hf * 256;
            const char* bS = dyn + BST_OFF + (r >> 4) * 528 + hf * 256;
            char* pA = dyn + r * 272 + hf * 128;
            #pragma unroll
            for (int c = 0; c < 8; c++) {
                float4 ya  = *(const float4*)(yS + 32 * c);
                float4 yb  = *(const float4*)(yS + 32 * c + 16);
                float4 ba  = *(const float4*)(bS + 32 * c);
                float4 bbv = *(const float4*)(bS + 32 * c + 16);
                __half2 h0, h1, h2, h3;
                h0.x = __float2half_rn(fmaxf(ba.x + ya.x, 0.f));
                h0.y = __float2half_rn(fmaxf(ba.y + ya.y, 0.f));
                h1.x = __float2half_rn(fmaxf(ba.z + ya.z, 0.f));
                h1.y = __float2half_rn(fmaxf(ba.w + ya.w, 0.f));
                h2.x = __float2half_rn(fmaxf(bbv.x + yb.x, 0.f));
                h2.y = __float2half_rn(fmaxf(bbv.y + yb.y, 0.f));
                h3.x = __float2half_rn(fmaxf(bbv.z + yb.z, 0.f));
                h3.y = __float2half_rn(fmaxf(bbv.w + yb.w, 0.f));
                uint4 q;
                q.x = *(uint32_t*)&h0; q.y = *(uint32_t*)&h1;
                q.z = *(uint32_t*)&h2; q.w = *(uint32_t*)&h3;
                *(uint4*)(pA + 16 * c) = q;
            }
        }
        if (tid < 8 && nxt < ngrp) s_pts[par ^ 1][tid] = g_list[nxt * 8 + tid];
        __syncthreads();    // A ready; staging drained; s_pts[next] visible

        if (nxt < ngrp) {   // prefetch next group (overlaps MMA + epilogue)
            const int point = s_pts[par ^ 1][r >> 4];
            const int nb = g_idx[point * Kq + (r & 15)];
            const char* src = (const char*)(g_y + (size_t)((point >> 7) * Pq + nb) * Hq) + hf * 256;
            #pragma unroll
            for (int j = 0; j < 16; j++) CP_ASYNC16(yDst + 16 * j, src + 16 * j);
            const char* bsrc = (const char*)(g_base + (size_t)s_pts[par ^ 1][tid >> 5] * Hq) + (tid & 31) * 16;
            CP_ASYNC16(bDst, bsrc);
        }
        CP_COMMIT();

        float acc[4][8][4];
        #pragma unroll
        for (int i = 0; i < 4; i++)
            #pragma unroll
            for (int nt = 0; nt < 8; nt++)
                #pragma unroll
                for (int c = 0; c < 4; c++) acc[i][nt][c] = 0.f;

        #pragma unroll 1
        for (int s = 0; s < 8; s++) {
            const uint32_t ks = s * 32;
            unsigned aF[4][4];
            #pragma unroll
            for (int i = 0; i < 4; i++) LDSM_X4(aF[i], aAddr[i] + ks);
            #pragma unroll
            for (int j = 0; j < 4; j++) {
                unsigned bF[4];
                LDSM_X4(bF, bAddr[j] + ks);
                #pragma unroll
                for (int i = 0; i < 4; i++) {
                    mma_f16(acc[i][2 * j],     aF[i], bF[0], bF[1]);
                    mma_f16(acc[i][2 * j + 1], aF[i], bF[2], bF[3]);
                }
            }
        }

        // epilogue: relu(+bias), mean over 16 edge rows, write out
        #pragma unroll
        for (int i = 0; i < 4; i++) {
            const int point = s_pts[par][pg * 4 + i];
            float* orow = out + (size_t)point * (Oq + 1);
            #pragma unroll
            for (int nt = 0; nt < 8; nt++) {
                float s0 = fmaxf(acc[i][nt][0] + bias[nt][0], 0.f)
                         + fmaxf(acc[i][nt][2] + bias[nt][0], 0.f);
                float s1 = fmaxf(acc[i][nt][1] + bias[nt][1], 0.f)
                         + fmaxf(acc[i][nt][3] + bias[nt][1], 0.f);
                #pragma unroll
                for (int o = 4; o < 32; o <<= 1) {
                    s0 += __shfl_xor_sync(0xffffffffu, s0, o);
                    s1 += __shfl_xor_sync(0xffffffffu, s1, o);
                }
                if ((lane >> 2) == 0) {
                    orow[n0 + nt * 8 + 2 * t4]     = s0 * (1.f / 16.f);
                    orow[n0 + nt * 8 + 2 * t4 + 1] = s1 * (1.f / 16.f);
                }
            }
            if (nch == 0 && lane == 0) orow[Oq] = 1.f;
        }
        par ^= 1;
    }
}

// ---------------------------------------------------------------------------
extern "C" void kernel_launch(void* const* d_in, const int* in_sizes, int n_in,
                              void* d_out, int out_size) {
    (void)in_sizes; (void)n_in; (void)out_size;
    const float* x  = (const float*)d_in[0];
    const float* W1 = (const float*)d_in[1];
    const float* b1 = (const float*)d_in[2];
    const float* W2 = (const float*)d_in[3];
    const float* b2 = (const float*)d_in[4];
    float* out = (float*)d_out;

    cudaFuncSetAttribute(mlp_kernel, cudaFuncAttributeMaxDynamicSharedMemorySize, SMEM_TOT);

    prep_kernel<<<256, 128>>>(W2);                  // resets g_cnt before embed's atomics
    knn_kernel<<<dim3(Bq, 2), 64>>>(x);
    embed_kernel<<<Bq * Pq / 16, 256>>>(x, W1, b1);
    zero_kernel<<<Bq * Pq / 8, 256>>>(x, out);
    mlp_kernel<<<148, 256, SMEM_TOT>>>(b2, out);
}

// round 14
// speedup vs baseline: 3.5934x; 1.2055x over previous
#include <cuda_runtime.h>
#include <cuda_fp16.h>
#include <cstdint>

#define Bq 256
#define Pq 128
#define Kq 16
#define Hq 128
#define Oq 256
#define LDH 136            // A/B tile row stride (halves); 272 bytes

__device__ int  g_idx [Bq*Pq*Kq];
__device__ __align__(256) __half g_base[Bq*Pq*Hq];
__device__ __align__(256) __half g_y   [Bq*Pq*Hq];
__device__ __align__(16)  __half g_wH  [Oq*LDH];   // W2^T fp16 [n][k]
__device__ int g_cnt;
__device__ int g_list[Bq*Pq];

// ---------------- K1: exact KNN (top-17, ties->lower idx, drop self) -------
// [t][j] smem layout, stride 130 floats; float2 scan (exact order preserved)
__global__ __launch_bounds__(64) void knn_kernel(const float* __restrict__ x) {
    const int b = blockIdx.x, half = blockIdx.y, t = threadIdx.x;
    __shared__ float scx[Pq], scy[Pq], sval[Pq];
    __shared__ float sdist[64 * 130];
    for (int j = t; j < Pq; j += 64) {
        const float* row = x + ((size_t)b * Pq + j) * 10;
        scx[j] = row[0]; scy[j] = row[1]; sval[j] = row[9];
    }
    __syncthreads();
    const int p = half * 64 + t;
    if (sval[p] <= 0.f) return;
    const float cx = scx[p], cy = scy[p];
    float* drow = sdist + t * 130;
    for (int j = 0; j < Pq; j += 2) {
        float dx0 = scx[j] - cx,     dy0 = scy[j] - cy;
        float dx1 = scx[j + 1] - cx, dy1 = scy[j + 1] - cy;
        float d0 = dx0 * dx0 + dy0 * dy0;
        float d1 = dx1 * dx1 + dy1 * dy1;
        if (sval[j] <= 0.f)     d0 = 1e9f;
        if (sval[j + 1] <= 0.f) d1 = 1e9f;
        *(float2*)(drow + j) = make_float2(d0, d1);
    }
    const int off = (b * Pq + p) * Kq;
    #pragma unroll 1
    for (int pass = 0; pass < Kq + 1; pass++) {
        float best = 3.0e38f; int bj = 0;
        for (int j = 0; j < Pq; j += 2) {
            float2 d = *(const float2*)(drow + j);
            if (d.x < best) { best = d.x; bj = j; }
            if (d.y < best) { best = d.y; bj = j + 1; }
        }
        drow[bj] = 3.4e38f;
        if (pass >= 1) g_idx[off + pass - 1] = bj;
    }
}

// ---------------- K2: layer-1 factorization -> fp16; list + dead-zero fused
// 8 points/block, 256 thr (2 h-groups x 128, 4 points each)
__global__ __launch_bounds__(256) void embed_kernel(const float* __restrict__ x,
                                                    const float* __restrict__ W1,
                                                    const float* __restrict__ b1,
                                                    float* __restrict__ out) {
    __shared__ float sx[8][10];
    const int tid = threadIdx.x;
    const int h = tid & 127, gsel = tid >> 7;
    const int p0 = blockIdx.x * 8;

    for (int i = tid; i < 80; i += 256) sx[i / 10][i % 10] = x[(size_t)p0 * 10 + i];
    float wa[9], wb[9];
    #pragma unroll
    for (int e = 0; e < 9; e++) {
        float a = W1[e * Hq + h], b = W1[(e + 9) * Hq + h];
        wa[e] = a - b; wb[e] = b;
    }
    const float bb = b1[h];
    __syncthreads();

    if (tid < 8 && sx[tid][9] > 0.f) {
        int s = atomicAdd(&g_cnt, 1);
        g_list[s] = p0 + tid;
    }
    #pragma unroll
    for (int q = 0; q < 4; q++) {
        const int lp = gsel * 4 + q;
        const int bp = p0 + lp;
        float base = bb, y = 0.f;
        #pragma unroll
        for (int e = 0; e < 9; e++) {
            float v = sx[lp][e];
            base = fmaf(v, wa[e], base);
            y    = fmaf(v, wb[e], y);
        }
        g_base[(size_t)bp * Hq + h] = __float2half_rn(base);
        g_y   [(size_t)bp * Hq + h] = __float2half_rn(y);
    }
    #pragma unroll 1
    for (int lp = 0; lp < 8; lp++) {          // zero dead output rows
        if (sx[lp][9] > 0.f) continue;
        float* orow = out + (size_t)(p0 + lp) * (Oq + 1);
        for (int i = tid; i < Oq + 1; i += 256) orow[i] = 0.f;
    }
}

// ---------------- prep: W2 -> fp16, transposed [n][k] + pad; reset list ----
__global__ __launch_bounds__(128) void prep_kernel(const float* __restrict__ W2) {
    const int i = blockIdx.x * 128 + threadIdx.x;   // i = k*256 + n
    if (i == 0) g_cnt = 0;
    g_list[i] = 0;                                  // pad slots -> point 0 (always live)
    const int k = i >> 8, n = i & 255;
    g_wH[n * LDH + k] = __float2half_rn(W2[i]);
}

// ---------------- helpers --------------------------------------------------
__device__ __forceinline__ uint32_t smem_u32(const void* p) {
    uint32_t a;
    asm("{ .reg .u64 t; cvta.to.shared.u64 t, %1; cvt.u32.u64 %0, t; }" : "=r"(a) : "l"(p));
    return a;
}
__device__ __forceinline__ void mma_f16(float* d, const unsigned* a,
                                        unsigned b0, unsigned b1) {
    asm volatile(
        "mma.sync.aligned.m16n8k16.row.col.f32.f16.f16.f32 "
        "{%0,%1,%2,%3},{%4,%5,%6,%7},{%8,%9},{%0,%1,%2,%3};"
        : "+f"(d[0]), "+f"(d[1]), "+f"(d[2]), "+f"(d[3])
        : "r"(a[0]), "r"(a[1]), "r"(a[2]), "r"(a[3]), "r"(b0), "r"(b1));
}
#define LDSM_X4(r, addr) \
    asm volatile("ldmatrix.sync.aligned.m8n8.x4.shared.b16 {%0,%1,%2,%3}, [%4];" \
        : "=r"((r)[0]), "=r"((r)[1]), "=r"((r)[2]), "=r"((r)[3]) : "r"(addr))
#define CP_ASYNC16(dst, src) \
    asm volatile("cp.async.cg.shared.global [%0], [%1], 16;" :: "r"(dst), "l"(src))
#define CP_COMMIT()  asm volatile("cp.async.commit_group;" ::: "memory")
#define CP_WAIT0()   asm volatile("cp.async.wait_group 0;"  ::: "memory")

#define B_BASE_OFF 34816u                 // A tile = 128*272 B
#define YST_OFF    104448u                // + B tile 69632
#define BST_OFF    139264u                // + y staging 128*272
#define SMEM_TOT   141440u                // + base staging 8*272

// ---------------- K3: persistent fp16 MLP, cp.async pipeline, half2 convert
__global__ __launch_bounds__(256, 1) void mlp_kernel(const float* __restrict__ b2,
                                                     float* __restrict__ out) {
    extern __shared__ __align__(16) char dyn[];
    __shared__ int s_pts[2][8];

    const int tid = threadIdx.x, warp = tid >> 5, lane = tid & 31;
    const int t4 = lane & 3;
    const int pg = warp >> 2, nch = warp & 3, n0 = nch * 64;
    const uint32_t sbase = smem_u32(dyn);

    {   // stage fp16 W2^T once per block
        const float4* sW = (const float4*)g_wH;
        float4* dW = (float4*)(dyn + B_BASE_OFF);
        for (int j = tid; j < Oq * LDH / 8; j += 256) dW[j] = sW[j];
    }

    // ldmatrix base addresses (identical mapping to validated R10-R13)
    uint32_t aAddr[4];
    #pragma unroll
    for (int i = 0; i < 4; i++)
        aAddr[i] = sbase + ((pg * 4 + i) * 16 + (lane & 15)) * 272 + (lane >> 4) * 16;
    uint32_t bAddr[4];
    #pragma unroll
    for (int j = 0; j < 4; j++)
        bAddr[j] = sbase + B_BASE_OFF +
                   (n0 + j * 16 + (lane & 7) + ((lane >> 4) << 3)) * 272 +
                   ((lane >> 3) & 1) * 16;

    float bias[8][2];
    #pragma unroll
    for (int nt = 0; nt < 8; nt++) {
        bias[nt][0] = b2[n0 + nt * 8 + 2 * t4];
        bias[nt][1] = b2[n0 + nt * 8 + 2 * t4 + 1];
    }

    // staging mapping: r = A row, hf = 64-col half; fp16 rows = 256B + 16 pad
    const int r = tid & 127, hf = tid >> 7;
    const uint32_t yDst = sbase + YST_OFF + r * 272 + hf * 128;
    const uint32_t bDst = sbase + BST_OFF + (tid >> 4) * 272 + (tid & 15) * 16;

    const int cnt = g_cnt, ngrp = (cnt + 7) >> 3, stride = gridDim.x;
    int grp = blockIdx.x;
    if (tid < 8 && grp < ngrp) s_pts[0][tid] = g_list[grp * 8 + tid];
    __syncthreads();    // W2 staged + s_pts[0] visible

    if (grp < ngrp) {   // prologue prefetch (fp16: 8 chunks y + 1 chunk base)
        const int point = s_pts[0][r >> 4];
        const int nb = g_idx[point * Kq + (r & 15)];
        const char* src = (const char*)(g_y + (size_t)((point >> 7) * Pq + nb) * Hq) + hf * 128;
        #pragma unroll
        for (int j = 0; j < 8; j++) CP_ASYNC16(yDst + 16 * j, src + 16 * j);
        if (tid < 128) {
            const char* bsrc = (const char*)(g_base + (size_t)s_pts[0][tid >> 4] * Hq) + (tid & 15) * 16;
            CP_ASYNC16(bDst, bsrc);
        }
    }
    CP_COMMIT();

    int par = 0;
    for (; grp < ngrp; grp += stride) {
        const int nxt = grp + stride;
        CP_WAIT0();
        __syncthreads();    // staging arrived; prev group's MMA/epilogue done

        {   // convert: A = hmax2(hadd2(y, base), 0)  (pure half2 smem pass)
            const char* yS = dyn + YST_OFF + r * 272 + hf * 128;
            const char* bS = dyn + BST_OFF + (r >> 4) * 272 + hf * 128;
            char* pA = dyn + r * 272 + hf * 128;
            const __half2 z2 = __float2half2_rn(0.f);
            #pragma unroll
            for (int c = 0; c < 8; c++) {
                __half2 y0 = *(const __half2*)(yS + 16 * c);
                __half2 y1 = *(const __half2*)(yS + 16 * c + 4);
                __half2 y2 = *(const __half2*)(yS + 16 * c + 8);
                __half2 y3 = *(const __half2*)(yS + 16 * c + 12);
                __half2 b0 = *(const __half2*)(bS + 16 * c);
                __half2 b1v = *(const __half2*)(bS + 16 * c + 4);
                __half2 b2v = *(const __half2*)(bS + 16 * c + 8);
                __half2 b3 = *(const __half2*)(bS + 16 * c + 12);
                __half2 q0 = __hmax2(__hadd2(y0, b0), z2);
                __half2 q1 = __hmax2(__hadd2(y1, b1v), z2);
                __half2 q2 = __hmax2(__hadd2(y2, b2v), z2);
                __half2 q3 = __hmax2(__hadd2(y3, b3), z2);
                uint4 q;
                q.x = *(uint32_t*)&q0; q.y = *(uint32_t*)&q1;
                q.z = *(uint32_t*)&q2; q.w = *(uint32_t*)&q3;
                *(uint4*)(pA + 16 * c) = q;
            }
        }
        if (tid < 8 && nxt < ngrp) s_pts[par ^ 1][tid] = g_list[nxt * 8 + tid];
        __syncthreads();    // A ready; staging drained; s_pts[next] visible

        if (nxt < ngrp) {   // prefetch next group (overlaps MMA + epilogue)
            const int point = s_pts[par ^ 1][r >> 4];
            const int nb = g_idx[point * Kq + (r & 15)];
            const char* src = (const char*)(g_y + (size_t)((point >> 7) * Pq + nb) * Hq) + hf * 128;
            #pragma unroll
            for (int j = 0; j < 8; j++) CP_ASYNC16(yDst + 16 * j, src + 16 * j);
            if (tid < 128) {
                const char* bsrc = (const char*)(g_base + (size_t)s_pts[par ^ 1][tid >> 4] * Hq) + (tid & 15) * 16;
                CP_ASYNC16(bDst, bsrc);
            }
        }
        CP_COMMIT();

        float acc[4][8][4];
        #pragma unroll
        for (int i = 0; i < 4; i++)
            #pragma unroll
            for (int nt = 0; nt < 8; nt++)
                #pragma unroll
                for (int c = 0; c < 4; c++) acc[i][nt][c] = 0.f;

        #pragma unroll 1
        for (int s = 0; s < 8; s++) {
            const uint32_t ks = s * 32;
            unsigned aF[4][4], bF[4][4];
            #pragma unroll
            for (int i = 0; i < 4; i++) LDSM_X4(aF[i], aAddr[i] + ks);
            #pragma unroll
            for (int j = 0; j < 4; j++) LDSM_X4(bF[j], bAddr[j] + ks);
            #pragma unroll
            for (int j = 0; j < 4; j++)
                #pragma unroll
                for (int i = 0; i < 4; i++) {
                    mma_f16(acc[i][2 * j],     aF[i], bF[j][0], bF[j][1]);
                    mma_f16(acc[i][2 * j + 1], aF[i], bF[j][2], bF[j][3]);
                }
        }

        // epilogue: relu(+bias), mean over 16 edge rows, write out
        #pragma unroll
        for (int i = 0; i < 4; i++) {
            const int point = s_pts[par][pg * 4 + i];
            float* orow = out + (size_t)point * (Oq + 1);
            #pragma unroll
            for (int nt = 0; nt < 8; nt++) {
                float s0 = fmaxf(acc[i][nt][0] + bias[nt][0], 0.f)
                         + fmaxf(acc[i][nt][2] + bias[nt][0], 0.f);
                float s1 = fmaxf(acc[i][nt][1] + bias[nt][1], 0.f)
                         + fmaxf(acc[i][nt][3] + bias[nt][1], 0.f);
                #pragma unroll
                for (int o = 4; o < 32; o <<= 1) {
                    s0 += __shfl_xor_sync(0xffffffffu, s0, o);
                    s1 += __shfl_xor_sync(0xffffffffu, s1, o);
                }
                if ((lane >> 2) == 0) {
                    orow[n0 + nt * 8 + 2 * t4]     = s0 * (1.f / 16.f);
                    orow[n0 + nt * 8 + 2 * t4 + 1] = s1 * (1.f / 16.f);
                }
            }
            if (nch == 0 && lane == 0) orow[Oq] = 1.f;
        }
        par ^= 1;
    }
}

// ---------------------------------------------------------------------------
extern "C" void kernel_launch(void* const* d_in, const int* in_sizes, int n_in,
                              void* d_out, int out_size) {
    (void)in_sizes; (void)n_in; (void)out_size;
    const float* x  = (const float*)d_in[0];
    const float* W1 = (const float*)d_in[1];
    const float* b1 = (const float*)d_in[2];
    const float* W2 = (const float*)d_in[3];
    const float* b2 = (const float*)d_in[4];
    float* out = (float*)d_out;

    cudaFuncSetAttribute(mlp_kernel, cudaFuncAttributeMaxDynamicSharedMemorySize, SMEM_TOT);

    prep_kernel<<<256, 128>>>(W2);                  // resets g_cnt before embed's atomics
    knn_kernel<<<dim3(Bq, 2), 64>>>(x);
    embed_kernel<<<Bq * Pq / 8, 256>>>(x, W1, b1, out);
    mlp_kernel<<<148, 256, SMEM_TOT>>>(b2, out);
}